// round 1
// baseline (speedup 1.0000x reference)
#include <cuda_runtime.h>
#include <cuda_bf16.h>

// Problem constants
#define B_TOT   16384
#define V_STEPS 20
#define F_IN    15
#define H_DIM   256
#define G3      768     // 3*H
#define KPAD    272     // cols: [0..14]=x, [15]=0 pad, [16..271]=h  (K for GRU & layer1)

// ---------------- static device scratch (no allocations allowed) ----------------
__device__ float g_WT[KPAD * G3];        // W_T[k][g]: concat(W_ih | 0 | W_hh), k-major
__device__ float g_bsum[G3];             // b_ih + b_hh
__device__ float g_W1p[1024 * KPAD];     // W1 padded to K=272 with the same col layout
__device__ float g_xin[B_TOT * KPAD];    // [x(15) | 0 | h(256)] per row
__device__ float g_x1[B_TOT * 1024];
__device__ float g_x2[B_TOT * 1024];
__device__ float g_x3[B_TOT * 512];
__device__ float g_x4[B_TOT * 256];

__device__ __forceinline__ float sigmoidf_(float x) {
    return __fdividef(1.f, 1.f + __expf(-x));
}
__device__ __forceinline__ float tanh_(float x) {
    // tanh(x) = 2*sigmoid(2x) - 1 ; saturates correctly at +-1 for large |x|
    return __fdividef(2.f, 1.f + __expf(-2.f * x)) - 1.f;
}

// ---------------- kernel 0: pack weights ----------------
// blocks [0,768): build W_T row-of-k layout + bsum; blocks [768,1792): pad W1 -> W1p
__global__ void pack_kernel(const float* __restrict__ W_ih, const float* __restrict__ W_hh,
                            const float* __restrict__ b_ih, const float* __restrict__ b_hh,
                            const float* __restrict__ W1) {
    int b = blockIdx.x;
    int k = threadIdx.x;            // 0..271
    if (b < G3) {
        float v;
        if (k < 15)       v = W_ih[b * 15 + k];
        else if (k == 15) v = 0.f;
        else              v = W_hh[b * 256 + (k - 16)];
        g_WT[k * G3 + b] = v;
        if (k == 0) g_bsum[b] = b_ih[b] + b_hh[b];
    } else {
        int n = b - G3;
        float v;
        if (k < 15)       v = W1[n * 271 + k];
        else if (k == 15) v = 0.f;
        else              v = W1[n * 271 + (k - 1)];   // W1 col 15+j -> packed col 16+j
        g_W1p[n * KPAD + k] = v;
    }
}

// ---------------- kernel 1: fused GRU over V=20 steps ----------------
// grid 128 blocks x 256 threads; block owns 128 batch rows.
// smem: Xs[128][272] (x|pad|h), Wt[8][384] (k-tile of 3 gates x 128 j), hst[64][256]
__global__ __launch_bounds__(256, 1)
void gru_kernel(const float* __restrict__ state, const float* __restrict__ b_ih) {
    extern __shared__ float smem[];
    float* Xs  = smem;                          // 128*272 = 34816 floats
    float* WtS = smem + 128 * KPAD;             // 8*384   =  3072 floats
    float* hst = WtS + 8 * 384;                 // 64*256  = 16384 floats
    float4* Wt4 = (float4*)WtS;
    const float4* WT4 = (const float4*)g_WT;    // row stride 768/4 = 192 float4

    const int tid = threadIdx.x;
    const int jt  = tid & 31;                   // j-thread within warp (0..31)
    const int rt  = tid >> 5;                   // row-thread = warp id (0..7)
    const int bbase = blockIdx.x * 128;

    // init h=0 and pad col
    for (int i = tid; i < 128 * KPAD; i += 256) Xs[i] = 0.f;
    __syncthreads();

    for (int t = 0; t < V_STEPS; t++) {
        // load x_t into cols 0..14 (ordered vs. subsequent reads by the kt=0 barriers)
        for (int i = tid; i < 128 * F_IN; i += 256) {
            int r = i / F_IN, f = i - r * F_IN;
            Xs[r * KPAD + f] = state[(bbase + r) * (V_STEPS * F_IN) + t * F_IN + f];
        }

        for (int rp = 0; rp < 2; rp++) {
            const int rbase = rp * 64;
            for (int jc = 0; jc < 2; jc++) {
                float aR[8][4], aZ[8][4], aN[8][4], aX[8][4];
                #pragma unroll
                for (int i = 0; i < 8; i++)
                    #pragma unroll
                    for (int j = 0; j < 4; j++) { aR[i][j]=0.f; aZ[i][j]=0.f; aN[i][j]=0.f; aX[i][j]=0.f; }

                for (int kt = 0; kt < KPAD / 8; kt++) {           // 34 k-tiles of 8
                    __syncthreads();
                    #pragma unroll 3
                    for (int i = tid; i < 768; i += 256) {        // 8 k x 96 float4
                        int k = i / 96, r = i - k * 96;
                        int gate = r >> 5, q = r & 31;
                        Wt4[i] = WT4[(kt * 8 + k) * 192 + gate * 64 + jc * 32 + q];
                    }
                    __syncthreads();
                    #pragma unroll
                    for (int k = 0; k < 8; k++) {
                        const int kg = kt * 8 + k;
                        float xv[8];
                        #pragma unroll
                        for (int i = 0; i < 8; i++)
                            xv[i] = Xs[(rbase + rt * 8 + i) * KPAD + kg];   // broadcast LDS
                        float4 wr = Wt4[k * 96 + jt];
                        float4 wz = Wt4[k * 96 + 32 + jt];
                        float4 wn = Wt4[k * 96 + 64 + jt];
                        #pragma unroll
                        for (int i = 0; i < 8; i++) {
                            aR[i][0] += xv[i]*wr.x; aR[i][1] += xv[i]*wr.y;
                            aR[i][2] += xv[i]*wr.z; aR[i][3] += xv[i]*wr.w;
                            aZ[i][0] += xv[i]*wz.x; aZ[i][1] += xv[i]*wz.y;
                            aZ[i][2] += xv[i]*wz.z; aZ[i][3] += xv[i]*wz.w;
                            aN[i][0] += xv[i]*wn.x; aN[i][1] += xv[i]*wn.y;
                            aN[i][2] += xv[i]*wn.z; aN[i][3] += xv[i]*wn.w;
                        }
                        if (kg < 15) {   // x-side contribution to n gate kept separately
                            #pragma unroll
                            for (int i = 0; i < 8; i++) {
                                aX[i][0] += xv[i]*wn.x; aX[i][1] += xv[i]*wn.y;
                                aX[i][2] += xv[i]*wn.z; aX[i][3] += xv[i]*wn.w;
                            }
                        }
                    }
                }

                // gate math
                const int jb = jc * 128 + jt * 4;
                float4 bR = *(const float4*)(g_bsum + jb);
                float4 bZ = *(const float4*)(g_bsum + 256 + jb);
                float4 bN = *(const float4*)(g_bsum + 512 + jb);
                float4 bX = *(const float4*)(b_ih + 512 + jb);
                float brv[4] = {bR.x, bR.y, bR.z, bR.w};
                float bzv[4] = {bZ.x, bZ.y, bZ.z, bZ.w};
                float bnv[4] = {bN.x, bN.y, bN.z, bN.w};
                float bxv[4] = {bX.x, bX.y, bX.z, bX.w};
                #pragma unroll
                for (int i = 0; i < 8; i++) {
                    int row = rbase + rt * 8 + i;
                    float4 hp4 = *(float4*)&Xs[row * KPAD + 16 + jb];
                    float hpv[4] = {hp4.x, hp4.y, hp4.z, hp4.w};
                    float ov[4];
                    #pragma unroll
                    for (int jj = 0; jj < 4; jj++) {
                        float pr = aR[i][jj] + brv[jj];
                        float pz = aZ[i][jj] + bzv[jj];
                        float xn = aX[i][jj] + bxv[jj];
                        float hn = (aN[i][jj] + bnv[jj]) - xn;
                        float rg = sigmoidf_(pr);
                        float zg = sigmoidf_(pz);
                        float ng = tanh_(fmaf(rg, hn, xn));
                        ov[jj] = (1.f - zg) * ng + zg * hpv[jj];
                    }
                    *(float4*)&hst[(rt * 8 + i) * 256 + jb] =
                        make_float4(ov[0], ov[1], ov[2], ov[3]);
                }
            } // jc

            // commit h_new for this row-pass into X
            __syncthreads();
            for (int i = tid; i < 64 * 256; i += 256) {
                int rl = i >> 8, c = i & 255;
                Xs[(rbase + rl) * KPAD + 16 + c] = hst[i];
            }
        } // rp
        __syncthreads();
    } // t

    // epilogue: write x_in = [x(t=0) | 0 | h_final]
    for (int i = tid; i < 128 * KPAD; i += 256) {
        int r = i / KPAD, c = i - r * KPAD;
        float v;
        if (c < 15)       v = state[(bbase + r) * (V_STEPS * F_IN) + c];   // vehicle 0
        else if (c == 15) v = 0.f;
        else              v = Xs[i];
        g_xin[(bbase + r) * KPAD + c] = v;
    }
}

// ---------------- MLP GEMM: C[M,N] = relu(A[M,K] @ W[N,K]^T + b) ----------------
// block tile 128x64, thread tile 8x4, Kc=16. K and all ld's are multiples of 16/4.
__global__ __launch_bounds__(256)
void gemm_bias_relu(const float* __restrict__ A, const float* __restrict__ W,
                    const float* __restrict__ bias, float* __restrict__ C,
                    int K, int lda, int ldw, int ldc) {
    __shared__ float As[16][132];
    __shared__ float Ws[16][68];
    const int tid = threadIdx.x;
    const int nt = tid & 15, mt = tid >> 4;
    const int nb = blockIdx.x * 64, mb = blockIdx.y * 128;

    float acc[8][4];
    #pragma unroll
    for (int i = 0; i < 8; i++)
        #pragma unroll
        for (int j = 0; j < 4; j++) acc[i][j] = 0.f;

    for (int kt = 0; kt < K; kt += 16) {
        __syncthreads();
        #pragma unroll 2
        for (int i = tid; i < 512; i += 256) {        // A tile 128x16 as float4
            int row = i >> 2, kq = i & 3;
            float4 v = *(const float4*)(A + (mb + row) * lda + kt + kq * 4);
            As[kq * 4 + 0][row] = v.x; As[kq * 4 + 1][row] = v.y;
            As[kq * 4 + 2][row] = v.z; As[kq * 4 + 3][row] = v.w;
        }
        {
            int row = tid >> 2, kq = tid & 3;          // W tile 64x16 as float4
            float4 v = *(const float4*)(W + (nb + row) * ldw + kt + kq * 4);
            Ws[kq * 4 + 0][row] = v.x; Ws[kq * 4 + 1][row] = v.y;
            Ws[kq * 4 + 2][row] = v.z; Ws[kq * 4 + 3][row] = v.w;
        }
        __syncthreads();
        #pragma unroll
        for (int k = 0; k < 16; k++) {
            float4 a0 = *(float4*)&As[k][mt * 8];
            float4 a1 = *(float4*)&As[k][mt * 8 + 4];
            float4 w  = *(float4*)&Ws[k][nt * 4];
            float av[8] = {a0.x, a0.y, a0.z, a0.w, a1.x, a1.y, a1.z, a1.w};
            float wv[4] = {w.x, w.y, w.z, w.w};
            #pragma unroll
            for (int i = 0; i < 8; i++)
                #pragma unroll
                for (int j = 0; j < 4; j++) acc[i][j] += av[i] * wv[j];
        }
    }

    float4 bb = *(const float4*)(bias + nb + nt * 4);
    float bv[4] = {bb.x, bb.y, bb.z, bb.w};
    #pragma unroll
    for (int i = 0; i < 8; i++) {
        float4 o;
        o.x = fmaxf(acc[i][0] + bv[0], 0.f);
        o.y = fmaxf(acc[i][1] + bv[1], 0.f);
        o.z = fmaxf(acc[i][2] + bv[2], 0.f);
        o.w = fmaxf(acc[i][3] + bv[3], 0.f);
        *(float4*)(C + (mb + mt * 8 + i) * ldc + nb + nt * 4) = o;
    }
}

// ---------------- final layer: out = tanh(x4 @ Wp^T + bp), N=1 ----------------
__global__ __launch_bounds__(256)
void final_kernel(const float* __restrict__ x4, const float* __restrict__ Wp,
                  const float* __restrict__ bp, float* __restrict__ out) {
    int warp = (blockIdx.x * 256 + threadIdx.x) >> 5;
    int lane = threadIdx.x & 31;
    if (warp >= B_TOT) return;
    const float* row = x4 + warp * 256;
    float s = 0.f;
    #pragma unroll
    for (int c = lane; c < 256; c += 32) s += row[c] * Wp[c];
    #pragma unroll
    for (int o = 16; o; o >>= 1) s += __shfl_xor_sync(0xffffffffu, s, o);
    if (lane == 0) out[warp] = tanh_(s + bp[0]);
}

// ---------------- host launcher ----------------
extern "C" void kernel_launch(void* const* d_in, const int* in_sizes, int n_in,
                              void* d_out, int out_size) {
    const float* state = (const float*)d_in[0];
    const float* W_ih  = (const float*)d_in[1];
    const float* W_hh  = (const float*)d_in[2];
    const float* b_ih  = (const float*)d_in[3];
    const float* b_hh  = (const float*)d_in[4];
    const float* W1    = (const float*)d_in[5];
    const float* b1    = (const float*)d_in[6];
    const float* W2    = (const float*)d_in[7];
    const float* b2    = (const float*)d_in[8];
    const float* W3    = (const float*)d_in[9];
    const float* b3    = (const float*)d_in[10];
    const float* W4    = (const float*)d_in[11];
    const float* b4    = (const float*)d_in[12];
    const float* Wp    = (const float*)d_in[13];
    const float* bp    = (const float*)d_in[14];
    float* out = (float*)d_out;
    (void)in_sizes; (void)n_in; (void)out_size;

    void *pW1p, *pxin, *px1, *px2, *px3, *px4;
    cudaGetSymbolAddress(&pW1p, g_W1p);
    cudaGetSymbolAddress(&pxin, g_xin);
    cudaGetSymbolAddress(&px1,  g_x1);
    cudaGetSymbolAddress(&px2,  g_x2);
    cudaGetSymbolAddress(&px3,  g_x3);
    cudaGetSymbolAddress(&px4,  g_x4);

    pack_kernel<<<G3 + 1024, KPAD>>>(W_ih, W_hh, b_ih, b_hh, W1);

    constexpr int GRU_SMEM = (128 * KPAD + 8 * 384 + 64 * 256) * 4;   // 217,088 B
    cudaFuncSetAttribute(gru_kernel, cudaFuncAttributeMaxDynamicSharedMemorySize, GRU_SMEM);
    gru_kernel<<<128, 256, GRU_SMEM>>>(state, b_ih);

    // L1: [B,272] x [1024,272]^T
    gemm_bias_relu<<<dim3(16, 128), 256>>>((const float*)pxin, (const float*)pW1p, b1,
                                           (float*)px1, KPAD, KPAD, KPAD, 1024);
    // L2: [B,1024] x [1024,1024]^T
    gemm_bias_relu<<<dim3(16, 128), 256>>>((const float*)px1, W2, b2,
                                           (float*)px2, 1024, 1024, 1024, 1024);
    // L3: [B,1024] x [512,1024]^T
    gemm_bias_relu<<<dim3(8, 128), 256>>>((const float*)px2, W3, b3,
                                          (float*)px3, 1024, 1024, 1024, 512);
    // L4: [B,512] x [256,512]^T
    gemm_bias_relu<<<dim3(4, 128), 256>>>((const float*)px3, W4, b4,
                                          (float*)px4, 512, 512, 512, 256);
    // head
    final_kernel<<<B_TOT / 8, 256>>>((const float*)px4, Wp, bp, out);
}

// round 2
// speedup vs baseline: 1.1871x; 1.1871x over previous
#include <cuda_runtime.h>
#include <cuda_bf16.h>

// Problem constants
#define B_TOT   16384
#define V_STEPS 20
#define F_IN    15
#define H_DIM   256
#define G3      768     // 3*H
#define KPAD    272     // cols: [0..14]=x, [15]=0 pad, [16..271]=h  (K for GRU & layer1)

// ---------------- static device scratch (no allocations allowed) ----------------
__device__ float g_WT[KPAD * G3];        // W_T[k][g]: concat(W_ih | 0 | W_hh), k-major
__device__ float g_bsum[G3];             // b_ih + b_hh
__device__ float g_W1p[1024 * KPAD];     // W1 padded to K=272 with the same col layout
__device__ float g_xin[B_TOT * KPAD];    // [x(15) | 0 | h(256)] per row
__device__ float g_x1[B_TOT * 1024];
__device__ float g_x2[B_TOT * 1024];
__device__ float g_x3[B_TOT * 512];
__device__ float g_x4[B_TOT * 256];

__device__ __forceinline__ float sigmoidf_(float x) {
    return __fdividef(1.f, 1.f + __expf(-x));
}
__device__ __forceinline__ float tanh_(float x) {
    return __fdividef(2.f, 1.f + __expf(-2.f * x)) - 1.f;
}

// ---- packed fp32x2 helpers (SASS FFMA2 path; ptxas never emits this from C++) ----
typedef unsigned long long u64;
union F4U2 { float4 f4; u64 u2[2]; };

__device__ __forceinline__ u64 pack2(float lo, float hi) {
    u64 r; asm("mov.b64 %0, {%1, %2};" : "=l"(r) : "f"(lo), "f"(hi)); return r;
}
__device__ __forceinline__ u64 fma2(u64 a, u64 b, u64 c) {
    u64 d; asm("fma.rn.f32x2 %0, %1, %2, %3;" : "=l"(d) : "l"(a), "l"(b), "l"(c)); return d;
}
__device__ __forceinline__ float2 unpk2(u64 v) {
    float2 f; asm("mov.b64 {%0, %1}, %2;" : "=f"(f.x), "=f"(f.y) : "l"(v)); return f;
}

// ---------------- kernel 0: pack weights ----------------
__global__ void pack_kernel(const float* __restrict__ W_ih, const float* __restrict__ W_hh,
                            const float* __restrict__ b_ih, const float* __restrict__ b_hh,
                            const float* __restrict__ W1) {
    int b = blockIdx.x;
    int k = threadIdx.x;            // 0..271
    if (b < G3) {
        float v;
        if (k < 15)       v = W_ih[b * 15 + k];
        else if (k == 15) v = 0.f;
        else              v = W_hh[b * 256 + (k - 16)];
        g_WT[k * G3 + b] = v;
        if (k == 0) g_bsum[b] = b_ih[b] + b_hh[b];
    } else {
        int n = b - G3;
        float v;
        if (k < 15)       v = W1[n * 271 + k];
        else if (k == 15) v = 0.f;
        else              v = W1[n * 271 + (k - 1)];
        g_W1p[n * KPAD + k] = v;
    }
}

// ---------------- kernel 1: fused GRU over V=20 steps (f32x2 inner loop) ----------------
// grid 128 blocks x 256 threads; block owns 128 batch rows.
__global__ __launch_bounds__(256, 1)
void gru_kernel(const float* __restrict__ state, const float* __restrict__ b_ih) {
    extern __shared__ float smem[];
    float* Xs  = smem;                          // 128*272 = 34816 floats
    float* WtS = smem + 128 * KPAD;             // 8*384   =  3072 floats
    float* hst = WtS + 8 * 384;                 // 64*256  = 16384 floats
    float4* Wt4 = (float4*)WtS;
    const float4* WT4 = (const float4*)g_WT;    // row stride 768/4 = 192 float4

    const int tid = threadIdx.x;
    const int jt  = tid & 31;
    const int rt  = tid >> 5;
    const int bbase = blockIdx.x * 128;

    for (int i = tid; i < 128 * KPAD; i += 256) Xs[i] = 0.f;
    __syncthreads();

    for (int t = 0; t < V_STEPS; t++) {
        for (int i = tid; i < 128 * F_IN; i += 256) {
            int r = i / F_IN, f = i - r * F_IN;
            Xs[r * KPAD + f] = state[(bbase + r) * (V_STEPS * F_IN) + t * F_IN + f];
        }

        for (int rp = 0; rp < 2; rp++) {
            const int rbase = rp * 64;
            for (int jc = 0; jc < 2; jc++) {
                const int jb = jc * 128 + jt * 4;

                u64 accR[8][2], accZ[8][2], accN[8][2], accX[8][2];
                #pragma unroll
                for (int i = 0; i < 8; i++) {
                    accR[i][0]=0ull; accR[i][1]=0ull;
                    accZ[i][0]=0ull; accZ[i][1]=0ull;
                    accN[i][0]=0ull; accN[i][1]=0ull;
                    accX[i][0]=0ull; accX[i][1]=0ull;
                }

                for (int kt = 0; kt < KPAD / 8; kt++) {           // 34 k-tiles of 8
                    __syncthreads();
                    #pragma unroll 3
                    for (int i = tid; i < 768; i += 256) {        // 8 k x 96 float4
                        int k = i / 96, r = i - k * 96;
                        int gate = r >> 5, q = r & 31;
                        Wt4[i] = WT4[(kt * 8 + k) * 192 + gate * 64 + jc * 32 + q];
                    }
                    __syncthreads();

                    if (kt < 2) {
                        // kg in [0,16): also accumulate x-side of n gate.
                        // (kg==15 is the zero-padded column, harmless.)
                        #pragma unroll
                        for (int k = 0; k < 8; k++) {
                            const int kg = kt * 8 + k;
                            u64 xp[8];
                            #pragma unroll
                            for (int i = 0; i < 8; i++) {
                                float xv = Xs[(rbase + rt * 8 + i) * KPAD + kg];
                                xp[i] = pack2(xv, xv);
                            }
                            F4U2 wr, wz, wn;
                            wr.f4 = Wt4[k * 96 + jt];
                            wz.f4 = Wt4[k * 96 + 32 + jt];
                            wn.f4 = Wt4[k * 96 + 64 + jt];
                            #pragma unroll
                            for (int i = 0; i < 8; i++) {
                                accR[i][0] = fma2(xp[i], wr.u2[0], accR[i][0]);
                                accR[i][1] = fma2(xp[i], wr.u2[1], accR[i][1]);
                                accZ[i][0] = fma2(xp[i], wz.u2[0], accZ[i][0]);
                                accZ[i][1] = fma2(xp[i], wz.u2[1], accZ[i][1]);
                                accN[i][0] = fma2(xp[i], wn.u2[0], accN[i][0]);
                                accN[i][1] = fma2(xp[i], wn.u2[1], accN[i][1]);
                                accX[i][0] = fma2(xp[i], wn.u2[0], accX[i][0]);
                                accX[i][1] = fma2(xp[i], wn.u2[1], accX[i][1]);
                            }
                        }
                        if (kt == 1) {
                            // aX complete: spill to its epilogue slot in hst, freeing regs
                            #pragma unroll
                            for (int i = 0; i < 8; i++) {
                                float2 lo = unpk2(accX[i][0]);
                                float2 hi = unpk2(accX[i][1]);
                                *(float4*)&hst[(rt * 8 + i) * 256 + jb] =
                                    make_float4(lo.x, lo.y, hi.x, hi.y);
                            }
                        }
                    } else {
                        #pragma unroll
                        for (int k = 0; k < 8; k++) {
                            const int kg = kt * 8 + k;
                            u64 xp[8];
                            #pragma unroll
                            for (int i = 0; i < 8; i++) {
                                float xv = Xs[(rbase + rt * 8 + i) * KPAD + kg];
                                xp[i] = pack2(xv, xv);
                            }
                            F4U2 wr, wz, wn;
                            wr.f4 = Wt4[k * 96 + jt];
                            wz.f4 = Wt4[k * 96 + 32 + jt];
                            wn.f4 = Wt4[k * 96 + 64 + jt];
                            #pragma unroll
                            for (int i = 0; i < 8; i++) {
                                accR[i][0] = fma2(xp[i], wr.u2[0], accR[i][0]);
                                accR[i][1] = fma2(xp[i], wr.u2[1], accR[i][1]);
                                accZ[i][0] = fma2(xp[i], wz.u2[0], accZ[i][0]);
                                accZ[i][1] = fma2(xp[i], wz.u2[1], accZ[i][1]);
                                accN[i][0] = fma2(xp[i], wn.u2[0], accN[i][0]);
                                accN[i][1] = fma2(xp[i], wn.u2[1], accN[i][1]);
                            }
                        }
                    }
                }

                // gate math
                float4 bR = *(const float4*)(g_bsum + jb);
                float4 bZ = *(const float4*)(g_bsum + 256 + jb);
                float4 bN = *(const float4*)(g_bsum + 512 + jb);
                float4 bX = *(const float4*)(b_ih + 512 + jb);
                float brv[4] = {bR.x, bR.y, bR.z, bR.w};
                float bzv[4] = {bZ.x, bZ.y, bZ.z, bZ.w};
                float bnv[4] = {bN.x, bN.y, bN.z, bN.w};
                float bxv[4] = {bX.x, bX.y, bX.z, bX.w};
                #pragma unroll
                for (int i = 0; i < 8; i++) {
                    int row = rbase + rt * 8 + i;
                    float4 hp4 = *(float4*)&Xs[row * KPAD + 16 + jb];
                    float hpv[4] = {hp4.x, hp4.y, hp4.z, hp4.w};
                    float4 xn4 = *(float4*)&hst[(rt * 8 + i) * 256 + jb];  // spilled aX
                    float xnv[4] = {xn4.x, xn4.y, xn4.z, xn4.w};
                    float2 r01 = unpk2(accR[i][0]), r23 = unpk2(accR[i][1]);
                    float2 z01 = unpk2(accZ[i][0]), z23 = unpk2(accZ[i][1]);
                    float2 n01 = unpk2(accN[i][0]), n23 = unpk2(accN[i][1]);
                    float aRv[4] = {r01.x, r01.y, r23.x, r23.y};
                    float aZv[4] = {z01.x, z01.y, z23.x, z23.y};
                    float aNv[4] = {n01.x, n01.y, n23.x, n23.y};
                    float ov[4];
                    #pragma unroll
                    for (int jj = 0; jj < 4; jj++) {
                        float pr = aRv[jj] + brv[jj];
                        float pz = aZv[jj] + bzv[jj];
                        float xn = xnv[jj] + bxv[jj];
                        float hn = (aNv[jj] + bnv[jj]) - xnv[jj] - xn + xnv[jj];
                        // hn = h-side preact + b_hh_n  == (aN + bsum_n) - (aX + b_ih_n)
                        hn = (aNv[jj] + bnv[jj]) - xn;
                        float rg = sigmoidf_(pr);
                        float zg = sigmoidf_(pz);
                        float ng = tanh_(fmaf(rg, hn, xn));
                        ov[jj] = (1.f - zg) * ng + zg * hpv[jj];
                    }
                    *(float4*)&hst[(rt * 8 + i) * 256 + jb] =
                        make_float4(ov[0], ov[1], ov[2], ov[3]);
                }
            } // jc

            __syncthreads();
            for (int i = tid; i < 64 * 256; i += 256) {
                int rl = i >> 8, c = i & 255;
                Xs[(rbase + rl) * KPAD + 16 + c] = hst[i];
            }
        } // rp
        __syncthreads();
    } // t

    // epilogue: write x_in = [x(t=0) | 0 | h_final]
    for (int i = tid; i < 128 * KPAD; i += 256) {
        int r = i / KPAD, c = i - r * KPAD;
        float v;
        if (c < 15)       v = state[(bbase + r) * (V_STEPS * F_IN) + c];
        else if (c == 15) v = 0.f;
        else              v = Xs[i];
        g_xin[(bbase + r) * KPAD + c] = v;
    }
}

// ---------------- MLP GEMM: C = relu(A @ W^T + b), f32x2 row-paired ----------------
__global__ __launch_bounds__(256)
void gemm_bias_relu(const float* __restrict__ A, const float* __restrict__ W,
                    const float* __restrict__ bias, float* __restrict__ C,
                    int K, int lda, int ldw, int ldc) {
    __shared__ float As[16][132];
    __shared__ float Ws[16][68];
    const int tid = threadIdx.x;
    const int nt = tid & 15, mt = tid >> 4;
    const int nb = blockIdx.x * 64, mb = blockIdx.y * 128;

    u64 acc[4][4];   // [row-pair][j]
    #pragma unroll
    for (int p = 0; p < 4; p++)
        #pragma unroll
        for (int j = 0; j < 4; j++) acc[p][j] = 0ull;

    for (int kt = 0; kt < K; kt += 16) {
        __syncthreads();
        #pragma unroll 2
        for (int i = tid; i < 512; i += 256) {        // A tile 128x16 as float4
            int row = i >> 2, kq = i & 3;
            float4 v = *(const float4*)(A + (mb + row) * lda + kt + kq * 4);
            As[kq * 4 + 0][row] = v.x; As[kq * 4 + 1][row] = v.y;
            As[kq * 4 + 2][row] = v.z; As[kq * 4 + 3][row] = v.w;
        }
        {
            int row = tid >> 2, kq = tid & 3;          // W tile 64x16 as float4
            float4 v = *(const float4*)(W + (nb + row) * ldw + kt + kq * 4);
            Ws[kq * 4 + 0][row] = v.x; Ws[kq * 4 + 1][row] = v.y;
            Ws[kq * 4 + 2][row] = v.z; Ws[kq * 4 + 3][row] = v.w;
        }
        __syncthreads();
        #pragma unroll
        for (int k = 0; k < 16; k++) {
            F4U2 a0, a1;
            a0.f4 = *(float4*)&As[k][mt * 8];
            a1.f4 = *(float4*)&As[k][mt * 8 + 4];
            float4 w = *(float4*)&Ws[k][nt * 4];
            u64 wp[4] = { pack2(w.x, w.x), pack2(w.y, w.y),
                          pack2(w.z, w.z), pack2(w.w, w.w) };
            u64 ap[4] = { a0.u2[0], a0.u2[1], a1.u2[0], a1.u2[1] };
            #pragma unroll
            for (int p = 0; p < 4; p++)
                #pragma unroll
                for (int j = 0; j < 4; j++)
                    acc[p][j] = fma2(ap[p], wp[j], acc[p][j]);
        }
    }

    float4 bb = *(const float4*)(bias + nb + nt * 4);
    float bv[4] = {bb.x, bb.y, bb.z, bb.w};
    #pragma unroll
    for (int p = 0; p < 4; p++) {
        float2 c0 = unpk2(acc[p][0]);
        float2 c1 = unpk2(acc[p][1]);
        float2 c2 = unpk2(acc[p][2]);
        float2 c3 = unpk2(acc[p][3]);
        float4 e; // even row (2p)
        e.x = fmaxf(c0.x + bv[0], 0.f);
        e.y = fmaxf(c1.x + bv[1], 0.f);
        e.z = fmaxf(c2.x + bv[2], 0.f);
        e.w = fmaxf(c3.x + bv[3], 0.f);
        float4 o; // odd row (2p+1)
        o.x = fmaxf(c0.y + bv[0], 0.f);
        o.y = fmaxf(c1.y + bv[1], 0.f);
        o.z = fmaxf(c2.y + bv[2], 0.f);
        o.w = fmaxf(c3.y + bv[3], 0.f);
        *(float4*)(C + (mb + mt * 8 + 2 * p) * ldc + nb + nt * 4) = e;
        *(float4*)(C + (mb + mt * 8 + 2 * p + 1) * ldc + nb + nt * 4) = o;
    }
}

// ---------------- final layer: out = tanh(x4 @ Wp^T + bp), N=1 ----------------
__global__ __launch_bounds__(256)
void final_kernel(const float* __restrict__ x4, const float* __restrict__ Wp,
                  const float* __restrict__ bp, float* __restrict__ out) {
    int warp = (blockIdx.x * 256 + threadIdx.x) >> 5;
    int lane = threadIdx.x & 31;
    if (warp >= B_TOT) return;
    const float* row = x4 + warp * 256;
    float s = 0.f;
    #pragma unroll
    for (int c = lane; c < 256; c += 32) s += row[c] * Wp[c];
    #pragma unroll
    for (int o = 16; o; o >>= 1) s += __shfl_xor_sync(0xffffffffu, s, o);
    if (lane == 0) out[warp] = tanh_(s + bp[0]);
}

// ---------------- host launcher ----------------
extern "C" void kernel_launch(void* const* d_in, const int* in_sizes, int n_in,
                              void* d_out, int out_size) {
    const float* state = (const float*)d_in[0];
    const float* W_ih  = (const float*)d_in[1];
    const float* W_hh  = (const float*)d_in[2];
    const float* b_ih  = (const float*)d_in[3];
    const float* b_hh  = (const float*)d_in[4];
    const float* W1    = (const float*)d_in[5];
    const float* b1    = (const float*)d_in[6];
    const float* W2    = (const float*)d_in[7];
    const float* b2    = (const float*)d_in[8];
    const float* W3    = (const float*)d_in[9];
    const float* b3    = (const float*)d_in[10];
    const float* W4    = (const float*)d_in[11];
    const float* b4    = (const float*)d_in[12];
    const float* Wp    = (const float*)d_in[13];
    const float* bp    = (const float*)d_in[14];
    float* out = (float*)d_out;
    (void)in_sizes; (void)n_in; (void)out_size;

    void *pW1p, *pxin, *px1, *px2, *px3, *px4;
    cudaGetSymbolAddress(&pW1p, g_W1p);
    cudaGetSymbolAddress(&pxin, g_xin);
    cudaGetSymbolAddress(&px1,  g_x1);
    cudaGetSymbolAddress(&px2,  g_x2);
    cudaGetSymbolAddress(&px3,  g_x3);
    cudaGetSymbolAddress(&px4,  g_x4);

    pack_kernel<<<G3 + 1024, KPAD>>>(W_ih, W_hh, b_ih, b_hh, W1);

    constexpr int GRU_SMEM = (128 * KPAD + 8 * 384 + 64 * 256) * 4;   // 217,088 B
    cudaFuncSetAttribute(gru_kernel, cudaFuncAttributeMaxDynamicSharedMemorySize, GRU_SMEM);
    gru_kernel<<<128, 256, GRU_SMEM>>>(state, b_ih);

    gemm_bias_relu<<<dim3(16, 128), 256>>>((const float*)pxin, (const float*)pW1p, b1,
                                           (float*)px1, KPAD, KPAD, KPAD, 1024);
    gemm_bias_relu<<<dim3(16, 128), 256>>>((const float*)px1, W2, b2,
                                           (float*)px2, 1024, 1024, 1024, 1024);
    gemm_bias_relu<<<dim3(8, 128), 256>>>((const float*)px2, W3, b3,
                                          (float*)px3, 1024, 1024, 1024, 512);
    gemm_bias_relu<<<dim3(4, 128), 256>>>((const float*)px3, W4, b4,
                                          (float*)px4, 512, 512, 512, 256);
    final_kernel<<<B_TOT / 8, 256>>>((const float*)px4, Wp, bp, out);
}

// round 3
// speedup vs baseline: 1.1884x; 1.0012x over previous
#include <cuda_runtime.h>
#include <cuda_bf16.h>

// Problem constants
#define B_TOT   16384
#define V_STEPS 20
#define F_IN    15
#define H_DIM   256
#define G3      768     // 3*H
#define KPAD    272     // cols: [0..14]=x, [15]=0 pad, [16..271]=h  (K for GRU & layer1)

// ---------------- static device scratch (no allocations allowed) ----------------
__device__ float g_WT[KPAD * G3];        // W_T[k][g]: concat(W_ih | 0 | W_hh), k-major
__device__ float g_bsum[G3];             // b_ih + b_hh
__device__ float g_W1p[1024 * KPAD];     // W1 padded to K=272 with the same col layout
__device__ float g_xin[B_TOT * KPAD];    // [x(15) | 0 | h(256)] per row
__device__ float g_x1[B_TOT * 1024];
__device__ float g_x2[B_TOT * 1024];
__device__ float g_x3[B_TOT * 512];
__device__ float g_x4[B_TOT * 256];

__device__ __forceinline__ float sigmoidf_(float x) {
    return __fdividef(1.f, 1.f + __expf(-x));
}
__device__ __forceinline__ float tanh_(float x) {
    return __fdividef(2.f, 1.f + __expf(-2.f * x)) - 1.f;
}

// ---- packed fp32x2 helpers (SASS FFMA2 path; ptxas never emits this from C++) ----
typedef unsigned long long u64;
union F4U2 { float4 f4; u64 u2[2]; };

__device__ __forceinline__ u64 pack2(float lo, float hi) {
    u64 r; asm("mov.b64 %0, {%1, %2};" : "=l"(r) : "f"(lo), "f"(hi)); return r;
}
__device__ __forceinline__ u64 fma2(u64 a, u64 b, u64 c) {
    u64 d; asm("fma.rn.f32x2 %0, %1, %2, %3;" : "=l"(d) : "l"(a), "l"(b), "l"(c)); return d;
}
__device__ __forceinline__ float2 unpk2(u64 v) {
    float2 f; asm("mov.b64 {%0, %1}, %2;" : "=f"(f.x), "=f"(f.y) : "l"(v)); return f;
}

// ---------------- kernel 0: pack weights ----------------
__global__ void pack_kernel(const float* __restrict__ W_ih, const float* __restrict__ W_hh,
                            const float* __restrict__ b_ih, const float* __restrict__ b_hh,
                            const float* __restrict__ W1) {
    int b = blockIdx.x;
    int k = threadIdx.x;            // 0..271
    if (b < G3) {
        float v;
        if (k < 15)       v = W_ih[b * 15 + k];
        else if (k == 15) v = 0.f;
        else              v = W_hh[b * 256 + (k - 16)];
        g_WT[k * G3 + b] = v;
        if (k == 0) g_bsum[b] = b_ih[b] + b_hh[b];
    } else {
        int n = b - G3;
        float v;
        if (k < 15)       v = W1[n * 271 + k];
        else if (k == 15) v = 0.f;
        else              v = W1[n * 271 + (k - 1)];
        g_W1p[n * KPAD + k] = v;
    }
}

// ---------------- kernel 1: fused GRU over V=20 steps (f32x2 inner loop) ----------------
// grid 128 blocks x 256 threads; block owns 128 batch rows.
__global__ __launch_bounds__(256, 1)
void gru_kernel(const float* __restrict__ state, const float* __restrict__ b_ih) {
    extern __shared__ float smem[];
    float* Xs  = smem;                          // 128*272 = 34816 floats
    float* WtS = smem + 128 * KPAD;             // 8*384   =  3072 floats
    float* hst = WtS + 8 * 384;                 // 64*256  = 16384 floats
    float4* Wt4 = (float4*)WtS;
    const float4* WT4 = (const float4*)g_WT;    // row stride 768/4 = 192 float4

    const int tid = threadIdx.x;
    const int jt  = tid & 31;
    const int rt  = tid >> 5;
    const int bbase = blockIdx.x * 128;

    for (int i = tid; i < 128 * KPAD; i += 256) Xs[i] = 0.f;
    __syncthreads();

    for (int t = 0; t < V_STEPS; t++) {
        for (int i = tid; i < 128 * F_IN; i += 256) {
            int r = i / F_IN, f = i - r * F_IN;
            Xs[r * KPAD + f] = state[(bbase + r) * (V_STEPS * F_IN) + t * F_IN + f];
        }

        for (int rp = 0; rp < 2; rp++) {
            const int rbase = rp * 64;
            for (int jc = 0; jc < 2; jc++) {
                const int jb = jc * 128 + jt * 4;

                u64 accR[8][2], accZ[8][2], accN[8][2], accX[8][2];
                #pragma unroll
                for (int i = 0; i < 8; i++) {
                    accR[i][0]=0ull; accR[i][1]=0ull;
                    accZ[i][0]=0ull; accZ[i][1]=0ull;
                    accN[i][0]=0ull; accN[i][1]=0ull;
                    accX[i][0]=0ull; accX[i][1]=0ull;
                }

                for (int kt = 0; kt < KPAD / 8; kt++) {           // 34 k-tiles of 8
                    __syncthreads();
                    #pragma unroll 3
                    for (int i = tid; i < 768; i += 256) {        // 8 k x 96 float4
                        int k = i / 96, r = i - k * 96;
                        int gate = r >> 5, q = r & 31;
                        Wt4[i] = WT4[(kt * 8 + k) * 192 + gate * 64 + jc * 32 + q];
                    }
                    __syncthreads();

                    if (kt < 2) {
                        // kg in [0,16): also accumulate x-side of n gate.
                        // (kg==15 is the zero-padded column, harmless.)
                        #pragma unroll
                        for (int k = 0; k < 8; k++) {
                            const int kg = kt * 8 + k;
                            u64 xp[8];
                            #pragma unroll
                            for (int i = 0; i < 8; i++) {
                                float xv = Xs[(rbase + rt * 8 + i) * KPAD + kg];
                                xp[i] = pack2(xv, xv);
                            }
                            F4U2 wr, wz, wn;
                            wr.f4 = Wt4[k * 96 + jt];
                            wz.f4 = Wt4[k * 96 + 32 + jt];
                            wn.f4 = Wt4[k * 96 + 64 + jt];
                            #pragma unroll
                            for (int i = 0; i < 8; i++) {
                                accR[i][0] = fma2(xp[i], wr.u2[0], accR[i][0]);
                                accR[i][1] = fma2(xp[i], wr.u2[1], accR[i][1]);
                                accZ[i][0] = fma2(xp[i], wz.u2[0], accZ[i][0]);
                                accZ[i][1] = fma2(xp[i], wz.u2[1], accZ[i][1]);
                                accN[i][0] = fma2(xp[i], wn.u2[0], accN[i][0]);
                                accN[i][1] = fma2(xp[i], wn.u2[1], accN[i][1]);
                                accX[i][0] = fma2(xp[i], wn.u2[0], accX[i][0]);
                                accX[i][1] = fma2(xp[i], wn.u2[1], accX[i][1]);
                            }
                        }
                        if (kt == 1) {
                            // aX complete: spill to its epilogue slot in hst, freeing regs
                            #pragma unroll
                            for (int i = 0; i < 8; i++) {
                                float2 lo = unpk2(accX[i][0]);
                                float2 hi = unpk2(accX[i][1]);
                                *(float4*)&hst[(rt * 8 + i) * 256 + jb] =
                                    make_float4(lo.x, lo.y, hi.x, hi.y);
                            }
                        }
                    } else {
                        #pragma unroll
                        for (int k = 0; k < 8; k++) {
                            const int kg = kt * 8 + k;
                            u64 xp[8];
                            #pragma unroll
                            for (int i = 0; i < 8; i++) {
                                float xv = Xs[(rbase + rt * 8 + i) * KPAD + kg];
                                xp[i] = pack2(xv, xv);
                            }
                            F4U2 wr, wz, wn;
                            wr.f4 = Wt4[k * 96 + jt];
                            wz.f4 = Wt4[k * 96 + 32 + jt];
                            wn.f4 = Wt4[k * 96 + 64 + jt];
                            #pragma unroll
                            for (int i = 0; i < 8; i++) {
                                accR[i][0] = fma2(xp[i], wr.u2[0], accR[i][0]);
                                accR[i][1] = fma2(xp[i], wr.u2[1], accR[i][1]);
                                accZ[i][0] = fma2(xp[i], wz.u2[0], accZ[i][0]);
                                accZ[i][1] = fma2(xp[i], wz.u2[1], accZ[i][1]);
                                accN[i][0] = fma2(xp[i], wn.u2[0], accN[i][0]);
                                accN[i][1] = fma2(xp[i], wn.u2[1], accN[i][1]);
                            }
                        }
                    }
                }

                // gate math
                float4 bR = *(const float4*)(g_bsum + jb);
                float4 bZ = *(const float4*)(g_bsum + 256 + jb);
                float4 bN = *(const float4*)(g_bsum + 512 + jb);
                float4 bX = *(const float4*)(b_ih + 512 + jb);
                float brv[4] = {bR.x, bR.y, bR.z, bR.w};
                float bzv[4] = {bZ.x, bZ.y, bZ.z, bZ.w};
                float bnv[4] = {bN.x, bN.y, bN.z, bN.w};
                float bxv[4] = {bX.x, bX.y, bX.z, bX.w};
                #pragma unroll
                for (int i = 0; i < 8; i++) {
                    int row = rbase + rt * 8 + i;
                    float4 hp4 = *(float4*)&Xs[row * KPAD + 16 + jb];
                    float hpv[4] = {hp4.x, hp4.y, hp4.z, hp4.w};
                    float4 xn4 = *(float4*)&hst[(rt * 8 + i) * 256 + jb];  // spilled aX
                    float xnv[4] = {xn4.x, xn4.y, xn4.z, xn4.w};
                    float2 r01 = unpk2(accR[i][0]), r23 = unpk2(accR[i][1]);
                    float2 z01 = unpk2(accZ[i][0]), z23 = unpk2(accZ[i][1]);
                    float2 n01 = unpk2(accN[i][0]), n23 = unpk2(accN[i][1]);
                    float aRv[4] = {r01.x, r01.y, r23.x, r23.y};
                    float aZv[4] = {z01.x, z01.y, z23.x, z23.y};
                    float aNv[4] = {n01.x, n01.y, n23.x, n23.y};
                    float ov[4];
                    #pragma unroll
                    for (int jj = 0; jj < 4; jj++) {
                        float pr = aRv[jj] + brv[jj];
                        float pz = aZv[jj] + bzv[jj];
                        float xn = xnv[jj] + bxv[jj];
                        float hn = (aNv[jj] + bnv[jj]) - xnv[jj] - xn + xnv[jj];
                        // hn = h-side preact + b_hh_n  == (aN + bsum_n) - (aX + b_ih_n)
                        hn = (aNv[jj] + bnv[jj]) - xn;
                        float rg = sigmoidf_(pr);
                        float zg = sigmoidf_(pz);
                        float ng = tanh_(fmaf(rg, hn, xn));
                        ov[jj] = (1.f - zg) * ng + zg * hpv[jj];
                    }
                    *(float4*)&hst[(rt * 8 + i) * 256 + jb] =
                        make_float4(ov[0], ov[1], ov[2], ov[3]);
                }
            } // jc

            __syncthreads();
            for (int i = tid; i < 64 * 256; i += 256) {
                int rl = i >> 8, c = i & 255;
                Xs[(rbase + rl) * KPAD + 16 + c] = hst[i];
            }
        } // rp
        __syncthreads();
    } // t

    // epilogue: write x_in = [x(t=0) | 0 | h_final]
    for (int i = tid; i < 128 * KPAD; i += 256) {
        int r = i / KPAD, c = i - r * KPAD;
        float v;
        if (c < 15)       v = state[(bbase + r) * (V_STEPS * F_IN) + c];
        else if (c == 15) v = 0.f;
        else              v = Xs[i];
        g_xin[(bbase + r) * KPAD + c] = v;
    }
}

// ---------------- MLP GEMM: C = relu(A @ W^T + b), f32x2 row-paired ----------------
__global__ __launch_bounds__(256)
void gemm_bias_relu(const float* __restrict__ A, const float* __restrict__ W,
                    const float* __restrict__ bias, float* __restrict__ C,
                    int K, int lda, int ldw, int ldc) {
    __shared__ float As[16][132];
    __shared__ float Ws[16][68];
    const int tid = threadIdx.x;
    const int nt = tid & 15, mt = tid >> 4;
    const int nb = blockIdx.x * 64, mb = blockIdx.y * 128;

    u64 acc[4][4];   // [row-pair][j]
    #pragma unroll
    for (int p = 0; p < 4; p++)
        #pragma unroll
        for (int j = 0; j < 4; j++) acc[p][j] = 0ull;

    for (int kt = 0; kt < K; kt += 16) {
        __syncthreads();
        #pragma unroll 2
        for (int i = tid; i < 512; i += 256) {        // A tile 128x16 as float4
            int row = i >> 2, kq = i & 3;
            float4 v = *(const float4*)(A + (mb + row) * lda + kt + kq * 4);
            As[kq * 4 + 0][row] = v.x; As[kq * 4 + 1][row] = v.y;
            As[kq * 4 + 2][row] = v.z; As[kq * 4 + 3][row] = v.w;
        }
        {
            int row = tid >> 2, kq = tid & 3;          // W tile 64x16 as float4
            float4 v = *(const float4*)(W + (nb + row) * ldw + kt + kq * 4);
            Ws[kq * 4 + 0][row] = v.x; Ws[kq * 4 + 1][row] = v.y;
            Ws[kq * 4 + 2][row] = v.z; Ws[kq * 4 + 3][row] = v.w;
        }
        __syncthreads();
        #pragma unroll
        for (int k = 0; k < 16; k++) {
            F4U2 a0, a1;
            a0.f4 = *(float4*)&As[k][mt * 8];
            a1.f4 = *(float4*)&As[k][mt * 8 + 4];
            float4 w = *(float4*)&Ws[k][nt * 4];
            u64 wp[4] = { pack2(w.x, w.x), pack2(w.y, w.y),
                          pack2(w.z, w.z), pack2(w.w, w.w) };
            u64 ap[4] = { a0.u2[0], a0.u2[1], a1.u2[0], a1.u2[1] };
            #pragma unroll
            for (int p = 0; p < 4; p++)
                #pragma unroll
                for (int j = 0; j < 4; j++)
                    acc[p][j] = fma2(ap[p], wp[j], acc[p][j]);
        }
    }

    float4 bb = *(const float4*)(bias + nb + nt * 4);
    float bv[4] = {bb.x, bb.y, bb.z, bb.w};
    #pragma unroll
    for (int p = 0; p < 4; p++) {
        float2 c0 = unpk2(acc[p][0]);
        float2 c1 = unpk2(acc[p][1]);
        float2 c2 = unpk2(acc[p][2]);
        float2 c3 = unpk2(acc[p][3]);
        float4 e; // even row (2p)
        e.x = fmaxf(c0.x + bv[0], 0.f);
        e.y = fmaxf(c1.x + bv[1], 0.f);
        e.z = fmaxf(c2.x + bv[2], 0.f);
        e.w = fmaxf(c3.x + bv[3], 0.f);
        float4 o; // odd row (2p+1)
        o.x = fmaxf(c0.y + bv[0], 0.f);
        o.y = fmaxf(c1.y + bv[1], 0.f);
        o.z = fmaxf(c2.y + bv[2], 0.f);
        o.w = fmaxf(c3.y + bv[3], 0.f);
        *(float4*)(C + (mb + mt * 8 + 2 * p) * ldc + nb + nt * 4) = e;
        *(float4*)(C + (mb + mt * 8 + 2 * p + 1) * ldc + nb + nt * 4) = o;
    }
}

// ---------------- final layer: out = tanh(x4 @ Wp^T + bp), N=1 ----------------
__global__ __launch_bounds__(256)
void final_kernel(const float* __restrict__ x4, const float* __restrict__ Wp,
                  const float* __restrict__ bp, float* __restrict__ out) {
    int warp = (blockIdx.x * 256 + threadIdx.x) >> 5;
    int lane = threadIdx.x & 31;
    if (warp >= B_TOT) return;
    const float* row = x4 + warp * 256;
    float s = 0.f;
    #pragma unroll
    for (int c = lane; c < 256; c += 32) s += row[c] * Wp[c];
    #pragma unroll
    for (int o = 16; o; o >>= 1) s += __shfl_xor_sync(0xffffffffu, s, o);
    if (lane == 0) out[warp] = tanh_(s + bp[0]);
}

// ---------------- host launcher ----------------
extern "C" void kernel_launch(void* const* d_in, const int* in_sizes, int n_in,
                              void* d_out, int out_size) {
    const float* state = (const float*)d_in[0];
    const float* W_ih  = (const float*)d_in[1];
    const float* W_hh  = (const float*)d_in[2];
    const float* b_ih  = (const float*)d_in[3];
    const float* b_hh  = (const float*)d_in[4];
    const float* W1    = (const float*)d_in[5];
    const float* b1    = (const float*)d_in[6];
    const float* W2    = (const float*)d_in[7];
    const float* b2    = (const float*)d_in[8];
    const float* W3    = (const float*)d_in[9];
    const float* b3    = (const float*)d_in[10];
    const float* W4    = (const float*)d_in[11];
    const float* b4    = (const float*)d_in[12];
    const float* Wp    = (const float*)d_in[13];
    const float* bp    = (const float*)d_in[14];
    float* out = (float*)d_out;
    (void)in_sizes; (void)n_in; (void)out_size;

    void *pW1p, *pxin, *px1, *px2, *px3, *px4;
    cudaGetSymbolAddress(&pW1p, g_W1p);
    cudaGetSymbolAddress(&pxin, g_xin);
    cudaGetSymbolAddress(&px1,  g_x1);
    cudaGetSymbolAddress(&px2,  g_x2);
    cudaGetSymbolAddress(&px3,  g_x3);
    cudaGetSymbolAddress(&px4,  g_x4);

    pack_kernel<<<G3 + 1024, KPAD>>>(W_ih, W_hh, b_ih, b_hh, W1);

    constexpr int GRU_SMEM = (128 * KPAD + 8 * 384 + 64 * 256) * 4;   // 217,088 B
    cudaFuncSetAttribute(gru_kernel, cudaFuncAttributeMaxDynamicSharedMemorySize, GRU_SMEM);
    gru_kernel<<<128, 256, GRU_SMEM>>>(state, b_ih);

    gemm_bias_relu<<<dim3(16, 128), 256>>>((const float*)pxin, (const float*)pW1p, b1,
                                           (float*)px1, KPAD, KPAD, KPAD, 1024);
    gemm_bias_relu<<<dim3(16, 128), 256>>>((const float*)px1, W2, b2,
                                           (float*)px2, 1024, 1024, 1024, 1024);
    gemm_bias_relu<<<dim3(8, 128), 256>>>((const float*)px2, W3, b3,
                                          (float*)px3, 1024, 1024, 1024, 512);
    gemm_bias_relu<<<dim3(4, 128), 256>>>((const float*)px3, W4, b4,
                                          (float*)px4, 512, 512, 512, 256);
    final_kernel<<<B_TOT / 8, 256>>>((const float*)px4, Wp, bp, out);
}